// round 5
// baseline (speedup 1.0000x reference)
#include <cuda_runtime.h>

// EnhancedLIFNeuron on GB300: Conv1d(1,1,5,'same') + spatial attention + LIF scan.
// B=128, T=128, F=2048. One thread = one (b,f) chain, fully independent:
// no SMEM, no syncs. Phase 1 streams x for the attention mean (closed form),
// Phase 2 re-reads x (L2-resident) through a 4-deep register prefetch ring
// while running the LIF recurrence. __launch_bounds__(128,8) -> 32 warps/SM,
// 8 independent chains per SMSP to hide the ~120-cycle serial step chain.

#define Tn 128
#define Fn 2048
#define Bn 128

__device__ __forceinline__ float fsqrt_ap(float a) {
    float r; asm("sqrt.approx.ftz.f32 %0,%1;" : "=f"(r) : "f"(a)); return r;
}
__device__ __forceinline__ float frcp_ap(float a) {
    float r; asm("rcp.approx.ftz.f32 %0,%1;" : "=f"(r) : "f"(a)); return r;
}

__global__ __launch_bounds__(128, 8)
void lif_kernel(const float* __restrict__ x,
                const float* __restrict__ thr0p,
                const float* __restrict__ convw,
                const float* __restrict__ convb,
                const float* __restrict__ sap,
                float* __restrict__ out)
{
    const int cid = blockIdx.x * 128 + threadIdx.x;   // chain id
    const int b   = cid >> 11;                        // / Fn
    const int f   = cid & (Fn - 1);
    const float* __restrict__ px = x + (size_t)b * Tn * Fn + f;

    // ---- scalars ----
    const float thr0 = __ldg(thr0p);
    const float w0 = __ldg(convw + 0), w1 = __ldg(convw + 1), w2 = __ldg(convw + 2),
                w3 = __ldg(convw + 3), w4 = __ldg(convw + 4);
    const float cb = __ldg(convb);
    const float sa = __ldg(sap);

    // ---- phase 1: streaming sum over t (high MLP) ----
    float a0 = 0.f, a1 = 0.f, a2 = 0.f, a3 = 0.f;
    #pragma unroll
    for (int t = 0; t < Tn; t += 8) {
        float l0 = __ldg(px + (size_t)(t + 0) * Fn);
        float l1 = __ldg(px + (size_t)(t + 1) * Fn);
        float l2 = __ldg(px + (size_t)(t + 2) * Fn);
        float l3 = __ldg(px + (size_t)(t + 3) * Fn);
        float l4 = __ldg(px + (size_t)(t + 4) * Fn);
        float l5 = __ldg(px + (size_t)(t + 5) * Fn);
        float l6 = __ldg(px + (size_t)(t + 6) * Fn);
        float l7 = __ldg(px + (size_t)(t + 7) * Fn);
        a0 += l0 + l4; a1 += l1 + l5; a2 += l2 + l6; a3 += l3 + l7;
    }
    const float S = (a0 + a1) + (a2 + a3);

    const float xb0   = __ldg(px);
    const float xb1   = __ldg(px + Fn);
    const float xb126 = __ldg(px + (size_t)126 * Fn);
    const float xb127 = __ldg(px + (size_t)127 * Fn);

    const float W = ((w0 + w1) + w2) + (w3 + w4);
    // sum_t conv_raw = W*S - (w3+w4)x0 - w4*x1 - w0*x126 - (w0+w1)*x127
    float mean = (W * S - (w3 + w4) * xb0 - w4 * xb1
                        - w0 * xb126 - (w0 + w1) * xb127) * (1.0f / Tn) + cb;
    const float attw  = 1.0f / (1.0f + __expf(-sa * mean));
    const float scale = 1.0f + 0.5f * attw;              // GAMMA = 0.5

    // ---- constants ----
    const float PI    = 3.14159265358979323846f;
    const float CARG  = PI * 0.5f;
    const float CTHR0 = 0.1f * thr0;                     // (1-ALPHA)*thr0
    const float CAVG  = 0.1f / 3.0f;                     // BETA/3
    // spike = atan(z)/(2pi)+0.25 via half-angle: t=z/(1+sqrt(1+z^2)),
    // spike = t*Q(t^2)+0.25, Q = (2/(2pi)) * deg-9 minimax
    const float INVPI = 1.0f / PI;
    const float P0 =  0.9998660f * INVPI;
    const float P1 = -0.3302995f * INVPI;
    const float P2 =  0.1801410f * INVPI;
    const float P3 = -0.0851330f * INVPI;
    const float P4 =  0.0208351f * INVPI;

    // fold attention scale into conv weights + bias
    const float v0 = w0 * scale, v1 = w1 * scale, v2 = w2 * scale,
                v3 = w3 * scale, v4 = w4 * scale, vb = cb * scale;

    // ---- phase 2: LIF with register prefetch ring (4 deep) ----
    float mem = 0.f, thr = thr0, h2 = 0.f, h12 = 0.f;    // h12 = h1+h2
    float xm2 = 0.f, xm1 = 0.f;
    float xc  = xb0;
    float xp1 = xb1;
    float xp2 = __ldg(px + (size_t)2 * Fn);
    float q0  = __ldg(px + (size_t)3 * Fn);
    float q1  = __ldg(px + (size_t)4 * Fn);
    float q2  = __ldg(px + (size_t)5 * Fn);
    float q3  = __ldg(px + (size_t)6 * Fn);

    float* __restrict__ opp = out + (size_t)b * Tn * Fn + f;

#define LIFSTEP(XNEW) do {                                                   \
        float xs = fmaf(v0, xm2,                                            \
                   fmaf(v1, xm1,                                            \
                   fmaf(v2, xc,                                             \
                   fmaf(v3, xp1,                                            \
                   fmaf(v4, xp2, vb)))));                                   \
        mem = fmaf(0.9f, mem, xs);                                          \
        float z  = (mem - thr) * CARG;                                      \
        float zz = z * z;                                                   \
        float sq = fsqrt_ap(1.0f + zz);                                     \
        float rt = frcp_ap(1.0f + sq);                                      \
        float tq = z * rt;                                                  \
        float tt = tq * tq;                                                 \
        float p  = fmaf(fmaf(fmaf(fmaf(P4, tt, P3), tt, P2), tt, P1), tt, P0); \
        float spike = fmaf(tq, p, 0.25f);                                   \
        float s3 = h12 + spike;                                             \
        thr = fmaf(0.9f, thr, fmaf(CAVG, s3, CTHR0));                       \
        mem = fmaf(-spike, thr, mem);                                       \
        *opp = spike; opp += Fn;                                            \
        h12 = h2 + spike; h2 = spike;                                       \
        xm2 = xm1; xm1 = xc; xc = xp1; xp1 = xp2; xp2 = (XNEW);             \
    } while (0)

    for (int g = 0; g < Tn; g += 4) {
        // prefetch next group's inputs (t = g+7 .. g+10), 4-7 steps ahead
        int tb = g + 7;
        float n0 = (tb + 0 < Tn) ? __ldg(px + (size_t)(tb + 0) * Fn) : 0.f;
        float n1 = (tb + 1 < Tn) ? __ldg(px + (size_t)(tb + 1) * Fn) : 0.f;
        float n2 = (tb + 2 < Tn) ? __ldg(px + (size_t)(tb + 2) * Fn) : 0.f;
        float n3 = (tb + 3 < Tn) ? __ldg(px + (size_t)(tb + 3) * Fn) : 0.f;

        LIFSTEP(q0);
        LIFSTEP(q1);
        LIFSTEP(q2);
        LIFSTEP(q3);

        q0 = n0; q1 = n1; q2 = n2; q3 = n3;
    }
#undef LIFSTEP

    // final membrane potential
    out[(size_t)Bn * Tn * Fn + (size_t)b * Fn + f] = mem;
}

extern "C" void kernel_launch(void* const* d_in, const int* in_sizes, int n_in,
                              void* d_out, int out_size)
{
    (void)in_sizes; (void)n_in; (void)out_size;
    const float* x    = (const float*)d_in[0];
    const float* thr0 = (const float*)d_in[1];
    const float* cw   = (const float*)d_in[2];
    const float* cbp  = (const float*)d_in[3];
    const float* sa   = (const float*)d_in[4];
    float* out = (float*)d_out;

    lif_kernel<<<(Bn * Fn) / 128, 128>>>(x, thr0, cw, cbp, sa, out);
}

// round 6
// speedup vs baseline: 1.1148x; 1.1148x over previous
#include <cuda_runtime.h>

// EnhancedLIFNeuron on GB300: Conv1d(1,1,5,'same') + spatial attention + LIF scan.
// B=128, T=128, F=2048. Each thread owns FOUR adjacent feature chains, run as
// TWO packed f32x2 streams (2-way ILP per warp on top of packed 2-wide math).
// No SMEM. Phase 1 streams x (float4) for the closed-form attention mean;
// phase 2 re-reads x (L2-resident) through a float4 prefetch ring while
// running the LIF recurrence. Grid = 512 blocks @ 4 blocks/SM = ONE wave.

#define Tn 128
#define Fn 2048
#define Bn 128

typedef unsigned long long u64;

__device__ __forceinline__ u64 pk(float lo, float hi) {
    u64 r; asm("mov.b64 %0,{%1,%2};" : "=l"(r) : "f"(lo), "f"(hi)); return r;
}
__device__ __forceinline__ void upk(u64 v, float& lo, float& hi) {
    asm("mov.b64 {%0,%1},%2;" : "=f"(lo), "=f"(hi) : "l"(v));
}
__device__ __forceinline__ u64 f2fma(u64 a, u64 b, u64 c) {
    u64 d; asm("fma.rn.f32x2 %0,%1,%2,%3;" : "=l"(d) : "l"(a), "l"(b), "l"(c)); return d;
}
__device__ __forceinline__ u64 f2mul(u64 a, u64 b) {
    u64 d; asm("mul.rn.f32x2 %0,%1,%2;" : "=l"(d) : "l"(a), "l"(b)); return d;
}
__device__ __forceinline__ u64 f2add(u64 a, u64 b) {
    u64 d; asm("add.rn.f32x2 %0,%1,%2;" : "=l"(d) : "l"(a), "l"(b)); return d;
}
__device__ __forceinline__ float frcp_ap(float a) {
    float r; asm("rcp.approx.ftz.f32 %0,%1;" : "=f"(r) : "f"(a)); return r;
}
__device__ __forceinline__ float fsqrt_ap(float a) {
    float r; asm("sqrt.approx.ftz.f32 %0,%1;" : "=f"(r) : "f"(a)); return r;
}

#define SMASK 0x8000000080000000ull

__global__ __launch_bounds__(128, 4)
void lif_kernel(const float* __restrict__ x,
                const float* __restrict__ thr0p,
                const float* __restrict__ convw,
                const float* __restrict__ convb,
                const float* __restrict__ sap,
                float* __restrict__ out)
{
    const int cid = blockIdx.x * 128 + threadIdx.x;   // quad-chain id
    const int b   = cid >> 9;                         // Fn/4 = 512 quads per batch
    const int fq  = cid & 511;                        // quad index; f = fq*4
    const float4* __restrict__ px4 =
        reinterpret_cast<const float4*>(x + (size_t)b * Tn * Fn) + fq;  // + t*512

    // ---- scalars ----
    const float thr0 = __ldg(thr0p);
    const float w0 = __ldg(convw + 0), w1 = __ldg(convw + 1), w2 = __ldg(convw + 2),
                w3 = __ldg(convw + 3), w4 = __ldg(convw + 4);
    const float cb = __ldg(convb);
    const float sa = __ldg(sap);

    // ---- phase 1: packed sums over t (float4 stream, high MLP) ----
    u64 aA0 = 0, aA1 = 0, aB0 = 0, aB1 = 0;
    #pragma unroll 8
    for (int t = 0; t < Tn; t += 2) {
        float4 v0 = __ldg(px4 + (t + 0) * 512);
        float4 v1 = __ldg(px4 + (t + 1) * 512);
        aA0 = f2add(aA0, pk(v0.x, v0.y));  aB0 = f2add(aB0, pk(v0.z, v0.w));
        aA1 = f2add(aA1, pk(v1.x, v1.y));  aB1 = f2add(aB1, pk(v1.z, v1.w));
    }
    float sA0, sA1, sB0, sB1;
    upk(f2add(aA0, aA1), sA0, sA1);
    upk(f2add(aB0, aB1), sB0, sB1);

    // boundary rows (L2/L1 hot)
    float4 r0   = __ldg(px4 + 0 * 512);
    float4 r1   = __ldg(px4 + 1 * 512);
    float4 r2   = __ldg(px4 + 2 * 512);
    float4 r126 = __ldg(px4 + 126 * 512);
    float4 r127 = __ldg(px4 + 127 * 512);

    // closed-form mean of conv output, then attention scale per lane
    const float W   = ((w0 + w1) + w2) + (w3 + w4);
    const float c34 = w3 + w4, c01 = w0 + w1;
#define MEANL(S, X0, X1, X126, X127) \
    ((W * (S) - c34 * (X0) - w4 * (X1) - w0 * (X126) - c01 * (X127)) * (1.0f/Tn) + cb)
    float m0 = MEANL(sA0, r0.x, r1.x, r126.x, r127.x);
    float m1 = MEANL(sA1, r0.y, r1.y, r126.y, r127.y);
    float m2 = MEANL(sB0, r0.z, r1.z, r126.z, r127.z);
    float m3 = MEANL(sB1, r0.w, r1.w, r126.w, r127.w);
#undef MEANL
    float sc0 = 1.0f + 0.5f / (1.0f + __expf(-sa * m0));   // GAMMA = 0.5
    float sc1 = 1.0f + 0.5f / (1.0f + __expf(-sa * m1));
    float sc2 = 1.0f + 0.5f / (1.0f + __expf(-sa * m2));
    float sc3 = 1.0f + 0.5f / (1.0f + __expf(-sa * m3));

    // scaled conv weights, packed per pair
    const u64 VA0 = pk(w0*sc0, w0*sc1), VB0 = pk(w0*sc2, w0*sc3);
    const u64 VA1 = pk(w1*sc0, w1*sc1), VB1 = pk(w1*sc2, w1*sc3);
    const u64 VA2 = pk(w2*sc0, w2*sc1), VB2 = pk(w2*sc2, w2*sc3);
    const u64 VA3 = pk(w3*sc0, w3*sc1), VB3 = pk(w3*sc2, w3*sc3);
    const u64 VA4 = pk(w4*sc0, w4*sc1), VB4 = pk(w4*sc2, w4*sc3);
    const u64 VAb = pk(cb*sc0, cb*sc1), VBb = pk(cb*sc2, cb*sc3);

    // ---- packed constants ----
    const float PI = 3.14159265358979323846f;
    const float INVPI = 1.0f / PI;
    const u64 DEC  = pk(0.9f, 0.9f);                  // DECAY == ALPHA
    const u64 CARG = pk(PI*0.5f, PI*0.5f);
    const u64 QRT  = pk(0.25f, 0.25f);
    const u64 ONE  = pk(1.0f, 1.0f);
    const u64 CAVG = pk(0.1f/3.0f, 0.1f/3.0f);
    const u64 CT0  = pk(0.1f*thr0, 0.1f*thr0);
    const u64 P0 = pk( 0.9998660f*INVPI,  0.9998660f*INVPI);
    const u64 P1 = pk(-0.3302995f*INVPI, -0.3302995f*INVPI);
    const u64 P2 = pk( 0.1801410f*INVPI,  0.1801410f*INVPI);
    const u64 P3 = pk(-0.0851330f*INVPI, -0.0851330f*INVPI);
    const u64 P4 = pk( 0.0208351f*INVPI,  0.0208351f*INVPI);

    // ---- LIF state, two packed pairs (A = f,f+1 ; B = f+2,f+3) ----
    u64 memA = 0, thrA = pk(thr0, thr0), h2A = 0, h12A = 0;
    u64 memB = 0, thrB = pk(thr0, thr0), h2B = 0, h12B = 0;
    u64 am2 = 0, am1 = 0, ac = pk(r0.x, r0.y), ap1 = pk(r1.x, r1.y), ap2 = pk(r2.x, r2.y);
    u64 bm2 = 0, bm1 = 0, bc = pk(r0.z, r0.w), bp1 = pk(r1.z, r1.w), bp2 = pk(r2.z, r2.w);

    float4 q0 = __ldg(px4 + 3*512);
    float4 q1 = __ldg(px4 + 4*512);
    float4 q2 = __ldg(px4 + 5*512);
    float4 q3 = __ldg(px4 + 6*512);
    const float4 z4 = make_float4(0.f, 0.f, 0.f, 0.f);

    ulonglong2* __restrict__ opp =
        reinterpret_cast<ulonglong2*>(out + (size_t)b * Tn * Fn) + fq;  // + t*512

    // one packed LIF step for one pair; returns spike (u64)
#define PAIRSTEP(mem, thr, h2, h12, xm2, xm1, xc, xp1, xp2, V0,V1,V2,V3,V4,Vb, XNEW, SPK) \
    do {                                                                     \
        u64 cv = f2fma(V0, xm2, f2fma(V1, xm1, f2fma(V2, xc,                 \
                 f2fma(V3, xp1, f2fma(V4, xp2, Vb)))));                      \
        mem = f2fma(DEC, mem, cv);                                           \
        u64 z  = f2mul(f2add(mem, thr ^ SMASK), CARG);                       \
        u64 o  = f2fma(z, z, ONE);                                           \
        float olo, ohi; upk(o, olo, ohi);                                    \
        float rlo = frcp_ap(1.0f + fsqrt_ap(olo));                           \
        float rhi = frcp_ap(1.0f + fsqrt_ap(ohi));                           \
        u64 tq = f2mul(z, pk(rlo, rhi));                                     \
        u64 tt = f2mul(tq, tq);                                              \
        u64 p  = f2fma(f2fma(f2fma(f2fma(P4, tt, P3), tt, P2), tt, P1), tt, P0); \
        u64 spike = f2fma(tq, p, QRT);                                       \
        u64 s3 = f2add(h12, spike);                                          \
        thr = f2fma(DEC, thr, f2fma(CAVG, s3, CT0));                         \
        mem = f2fma(spike ^ SMASK, thr, mem);                                \
        h12 = f2add(h2, spike); h2 = spike;                                  \
        xm2 = xm1; xm1 = xc; xc = xp1; xp1 = xp2; xp2 = (XNEW);              \
        SPK = spike;                                                         \
    } while (0)

#define QSTEP(Q) do {                                                        \
        u64 spA, spB;                                                        \
        PAIRSTEP(memA, thrA, h2A, h12A, am2, am1, ac, ap1, ap2,              \
                 VA0,VA1,VA2,VA3,VA4,VAb, pk((Q).x,(Q).y), spA);             \
        PAIRSTEP(memB, thrB, h2B, h12B, bm2, bm1, bc, bp1, bp2,              \
                 VB0,VB1,VB2,VB3,VB4,VBb, pk((Q).z,(Q).w), spB);             \
        ulonglong2 st; st.x = spA; st.y = spB;                               \
        *opp = st; opp += 512;                                               \
    } while (0)

    for (int g = 0; g < Tn; g += 4) {
        int tb = g + 7;   // prefetch 4-7 steps ahead
        float4 n0 = (tb + 0 < Tn) ? __ldg(px4 + (tb + 0) * 512) : z4;
        float4 n1 = (tb + 1 < Tn) ? __ldg(px4 + (tb + 1) * 512) : z4;
        float4 n2 = (tb + 2 < Tn) ? __ldg(px4 + (tb + 2) * 512) : z4;
        float4 n3 = (tb + 3 < Tn) ? __ldg(px4 + (tb + 3) * 512) : z4;

        QSTEP(q0); QSTEP(q1); QSTEP(q2); QSTEP(q3);

        q0 = n0; q1 = n1; q2 = n2; q3 = n3;
    }
#undef QSTEP
#undef PAIRSTEP

    // final membrane potential: out[B*T*F + b*F + f]
    ulonglong2 mf; mf.x = memA; mf.y = memB;
    *(reinterpret_cast<ulonglong2*>(out + (size_t)Bn * Tn * Fn + (size_t)b * Fn) + fq) = mf;
}

extern "C" void kernel_launch(void* const* d_in, const int* in_sizes, int n_in,
                              void* d_out, int out_size)
{
    (void)in_sizes; (void)n_in; (void)out_size;
    const float* x    = (const float*)d_in[0];
    const float* thr0 = (const float*)d_in[1];
    const float* cw   = (const float*)d_in[2];
    const float* cbp  = (const float*)d_in[3];
    const float* sa   = (const float*)d_in[4];
    float* out = (float*)d_out;

    lif_kernel<<<(Bn * Fn) / (128 * 4), 128>>>(x, thr0, cw, cbp, sa, out);
}

// round 11
// speedup vs baseline: 1.1690x; 1.0486x over previous
#include <cuda_runtime.h>

// EnhancedLIFNeuron on GB300: Conv1d(1,1,5,'same') + spatial attention + LIF scan.
// B=128, T=128, F=2048. Each thread owns FOUR adjacent feature chains as TWO
// packed f32x2 streams. No SMEM. Phase 1 streams x with default (evict_normal)
// loads; phase 2 re-reads with ld.global.cs (streaming, evict-first); all
// stores st.global.cs so the write stream doesn't evict x from L2.

#define Tn 128
#define Fn 2048
#define Bn 128

typedef unsigned long long u64;

__device__ __forceinline__ u64 pk(float lo, float hi) {
    u64 r; asm("mov.b64 %0,{%1,%2};" : "=l"(r) : "f"(lo), "f"(hi)); return r;
}
__device__ __forceinline__ void upk(u64 v, float& lo, float& hi) {
    asm("mov.b64 {%0,%1},%2;" : "=f"(lo), "=f"(hi) : "l"(v));
}
__device__ __forceinline__ u64 f2fma(u64 a, u64 b, u64 c) {
    u64 d; asm("fma.rn.f32x2 %0,%1,%2,%3;" : "=l"(d) : "l"(a), "l"(b), "l"(c)); return d;
}
__device__ __forceinline__ u64 f2mul(u64 a, u64 b) {
    u64 d; asm("mul.rn.f32x2 %0,%1,%2;" : "=l"(d) : "l"(a), "l"(b)); return d;
}
__device__ __forceinline__ u64 f2add(u64 a, u64 b) {
    u64 d; asm("add.rn.f32x2 %0,%1,%2;" : "=l"(d) : "l"(a), "l"(b)); return d;
}
__device__ __forceinline__ float frcp_ap(float a) {
    float r; asm("rcp.approx.ftz.f32 %0,%1;" : "=f"(r) : "f"(a)); return r;
}
__device__ __forceinline__ float fsqrt_ap(float a) {
    float r; asm("sqrt.approx.ftz.f32 %0,%1;" : "=f"(r) : "f"(a)); return r;
}
// phase-2 load: streaming (evict-first), legal at v4.f32 width
__device__ __forceinline__ float4 ld_once4(const float4* p) {
    float4 v;
    asm("ld.global.cs.v4.f32 {%0,%1,%2,%3},[%4];"
        : "=f"(v.x), "=f"(v.y), "=f"(v.z), "=f"(v.w) : "l"(p));
    return v;
}
// streaming store (evict-first)
__device__ __forceinline__ void st_stream2(ulonglong2* p, u64 a, u64 b) {
    asm volatile("st.global.cs.v2.u64 [%0],{%1,%2};" :: "l"(p), "l"(a), "l"(b) : "memory");
}

#define SMASK 0x8000000080000000ull

__global__ __launch_bounds__(128, 4)
void lif_kernel(const float* __restrict__ x,
                const float* __restrict__ thr0p,
                const float* __restrict__ convw,
                const float* __restrict__ convb,
                const float* __restrict__ sap,
                float* __restrict__ out)
{
    const int cid = blockIdx.x * 128 + threadIdx.x;   // quad-chain id
    const int b   = cid >> 9;                         // Fn/4 = 512 quads per batch
    const int fq  = cid & 511;
    const float4* __restrict__ px4 =
        reinterpret_cast<const float4*>(x + (size_t)b * Tn * Fn) + fq;  // + t*512

    // ---- scalars ----
    const float thr0 = __ldg(thr0p);
    const float w0 = __ldg(convw + 0), w1 = __ldg(convw + 1), w2 = __ldg(convw + 2),
                w3 = __ldg(convw + 3), w4 = __ldg(convw + 4);
    const float cb = __ldg(convb);
    const float sa = __ldg(sap);

    // ---- phase 1: packed sums over t (default loads keep x in L2) ----
    u64 aA0 = 0, aA1 = 0, aB0 = 0, aB1 = 0;
    float4 r0, r1, r2, r126, r127;
    #pragma unroll 8
    for (int t = 0; t < Tn; t += 2) {
        float4 v0 = __ldg(px4 + (t + 0) * 512);
        float4 v1 = __ldg(px4 + (t + 1) * 512);
        if (t == 0)   { r0 = v0; r1 = v1; }
        if (t == 2)   { r2 = v0; }
        if (t == 126) { r126 = v0; r127 = v1; }
        aA0 = f2add(aA0, pk(v0.x, v0.y));  aB0 = f2add(aB0, pk(v0.z, v0.w));
        aA1 = f2add(aA1, pk(v1.x, v1.y));  aB1 = f2add(aB1, pk(v1.z, v1.w));
    }
    float sA0, sA1, sB0, sB1;
    upk(f2add(aA0, aA1), sA0, sA1);
    upk(f2add(aB0, aB1), sB0, sB1);

    // closed-form mean of conv output, then attention scale per lane
    const float W   = ((w0 + w1) + w2) + (w3 + w4);
    const float c34 = w3 + w4, c01 = w0 + w1;
#define MEANL(S, X0, X1, X126, X127) \
    ((W * (S) - c34 * (X0) - w4 * (X1) - w0 * (X126) - c01 * (X127)) * (1.0f/Tn) + cb)
    float m0 = MEANL(sA0, r0.x, r1.x, r126.x, r127.x);
    float m1 = MEANL(sA1, r0.y, r1.y, r126.y, r127.y);
    float m2 = MEANL(sB0, r0.z, r1.z, r126.z, r127.z);
    float m3 = MEANL(sB1, r0.w, r1.w, r126.w, r127.w);
#undef MEANL
    float sc0 = 1.0f + 0.5f / (1.0f + __expf(-sa * m0));   // GAMMA = 0.5
    float sc1 = 1.0f + 0.5f / (1.0f + __expf(-sa * m1));
    float sc2 = 1.0f + 0.5f / (1.0f + __expf(-sa * m2));
    float sc3 = 1.0f + 0.5f / (1.0f + __expf(-sa * m3));

    // scaled conv weights, packed per pair
    const u64 VA0 = pk(w0*sc0, w0*sc1), VB0 = pk(w0*sc2, w0*sc3);
    const u64 VA1 = pk(w1*sc0, w1*sc1), VB1 = pk(w1*sc2, w1*sc3);
    const u64 VA2 = pk(w2*sc0, w2*sc1), VB2 = pk(w2*sc2, w2*sc3);
    const u64 VA3 = pk(w3*sc0, w3*sc1), VB3 = pk(w3*sc2, w3*sc3);
    const u64 VA4 = pk(w4*sc0, w4*sc1), VB4 = pk(w4*sc2, w4*sc3);
    const u64 VAb = pk(cb*sc0, cb*sc1), VBb = pk(cb*sc2, cb*sc3);

    // ---- packed constants ----
    const float PI = 3.14159265358979323846f;
    const float INVPI = 1.0f / PI;
    const u64 DEC  = pk(0.9f, 0.9f);                  // DECAY == ALPHA
    const u64 CARG = pk(PI*0.5f, PI*0.5f);
    const u64 QRT  = pk(0.25f, 0.25f);
    const u64 ONE  = pk(1.0f, 1.0f);
    const u64 CAVG = pk(0.1f/3.0f, 0.1f/3.0f);
    const u64 CT0  = pk(0.1f*thr0, 0.1f*thr0);
    const u64 P0 = pk( 0.9998660f*INVPI,  0.9998660f*INVPI);
    const u64 P1 = pk(-0.3302995f*INVPI, -0.3302995f*INVPI);
    const u64 P2 = pk( 0.1801410f*INVPI,  0.1801410f*INVPI);
    const u64 P3 = pk(-0.0851330f*INVPI, -0.0851330f*INVPI);
    const u64 P4 = pk( 0.0208351f*INVPI,  0.0208351f*INVPI);

    // ---- LIF state, two packed pairs (A = f,f+1 ; B = f+2,f+3) ----
    u64 memA = 0, thrA = pk(thr0, thr0), h2A = 0, h12A = 0;
    u64 memB = 0, thrB = pk(thr0, thr0), h2B = 0, h12B = 0;
    u64 am2 = 0, am1 = 0, ac = pk(r0.x, r0.y), ap1 = pk(r1.x, r1.y), ap2 = pk(r2.x, r2.y);
    u64 bm2 = 0, bm1 = 0, bc = pk(r0.z, r0.w), bp1 = pk(r1.z, r1.w), bp2 = pk(r2.z, r2.w);

    float4 q0 = ld_once4(px4 + 3*512);
    float4 q1 = ld_once4(px4 + 4*512);
    float4 q2 = ld_once4(px4 + 5*512);
    float4 q3 = ld_once4(px4 + 6*512);
    const float4 z4 = make_float4(0.f, 0.f, 0.f, 0.f);

    ulonglong2* __restrict__ opp =
        reinterpret_cast<ulonglong2*>(out + (size_t)b * Tn * Fn) + fq;  // + t*512

#define PAIRSTEP(mem, thr, h2, h12, xm2, xm1, xc, xp1, xp2, V0,V1,V2,V3,V4,Vb, XNEW, SPK) \
    do {                                                                     \
        u64 cv = f2fma(V0, xm2, f2fma(V1, xm1, f2fma(V2, xc,                 \
                 f2fma(V3, xp1, f2fma(V4, xp2, Vb)))));                      \
        mem = f2fma(DEC, mem, cv);                                           \
        u64 z  = f2mul(f2add(mem, thr ^ SMASK), CARG);                       \
        u64 o  = f2fma(z, z, ONE);                                           \
        float olo, ohi; upk(o, olo, ohi);                                    \
        float rlo = frcp_ap(1.0f + fsqrt_ap(olo));                           \
        float rhi = frcp_ap(1.0f + fsqrt_ap(ohi));                           \
        u64 tq = f2mul(z, pk(rlo, rhi));                                     \
        u64 tt = f2mul(tq, tq);                                              \
        u64 p  = f2fma(f2fma(f2fma(f2fma(P4, tt, P3), tt, P2), tt, P1), tt, P0); \
        u64 spike = f2fma(tq, p, QRT);                                       \
        u64 s3 = f2add(h12, spike);                                          \
        thr = f2fma(DEC, thr, f2fma(CAVG, s3, CT0));                         \
        mem = f2fma(spike ^ SMASK, thr, mem);                                \
        h12 = f2add(h2, spike); h2 = spike;                                  \
        xm2 = xm1; xm1 = xc; xc = xp1; xp1 = xp2; xp2 = (XNEW);              \
        SPK = spike;                                                         \
    } while (0)

#define QSTEP(Q) do {                                                        \
        u64 spA, spB;                                                        \
        PAIRSTEP(memA, thrA, h2A, h12A, am2, am1, ac, ap1, ap2,              \
                 VA0,VA1,VA2,VA3,VA4,VAb, pk((Q).x,(Q).y), spA);             \
        PAIRSTEP(memB, thrB, h2B, h12B, bm2, bm1, bc, bp1, bp2,              \
                 VB0,VB1,VB2,VB3,VB4,VBb, pk((Q).z,(Q).w), spB);             \
        st_stream2(opp, spA, spB); opp += 512;                               \
    } while (0)

    for (int g = 0; g < Tn; g += 4) {
        int tb = g + 7;   // prefetch 4-7 steps ahead
        float4 n0 = (tb + 0 < Tn) ? ld_once4(px4 + (tb + 0) * 512) : z4;
        float4 n1 = (tb + 1 < Tn) ? ld_once4(px4 + (tb + 1) * 512) : z4;
        float4 n2 = (tb + 2 < Tn) ? ld_once4(px4 + (tb + 2) * 512) : z4;
        float4 n3 = (tb + 3 < Tn) ? ld_once4(px4 + (tb + 3) * 512) : z4;

        QSTEP(q0); QSTEP(q1); QSTEP(q2); QSTEP(q3);

        q0 = n0; q1 = n1; q2 = n2; q3 = n3;
    }
#undef QSTEP
#undef PAIRSTEP

    // final membrane potential: out[B*T*F + b*F + f]
    st_stream2(reinterpret_cast<ulonglong2*>(out + (size_t)Bn * Tn * Fn + (size_t)b * Fn) + fq,
               memA, memB);
}

extern "C" void kernel_launch(void* const* d_in, const int* in_sizes, int n_in,
                              void* d_out, int out_size)
{
    (void)in_sizes; (void)n_in; (void)out_size;
    const float* x    = (const float*)d_in[0];
    const float* thr0 = (const float*)d_in[1];
    const float* cw   = (const float*)d_in[2];
    const float* cbp  = (const float*)d_in[3];
    const float* sa   = (const float*)d_in[4];
    float* out = (float*)d_out;

    lif_kernel<<<(Bn * Fn) / (128 * 4), 128>>>(x, thr0, cw, cbp, sa, out);
}